// round 14
// baseline (speedup 1.0000x reference)
#include <cuda_runtime.h>
#include <cuda_bf16.h>

// ---------------- problem constants ----------------
namespace {
constexpr int kD    = 1024;
constexpr int kHD   = 128;
constexpr int kEA   = 8;
constexpr int kEF   = 16;
constexpr int kFH   = 512;
constexpr int kMAXP = 64;
constexpr int kR    = 2 * kMAXP + 1;   // 129
constexpr int kB    = 4;
constexpr int kS    = 1024;
constexpr int kBS   = kB * kS;         // 4096
constexpr float kEPS = 1e-5f;
constexpr float kQScale = 0.08838834764831845f;   // 128^-0.5
constexpr int kPAD = 40;               // smem row pitch in bf16 for wmma tiles
}

typedef unsigned long long ull;

// ---------------- device scratch (allocation-free) ----------------
__device__ float g_kvbuf[(size_t)kBS * 256];              // packed [token][k(128)|v(128)]
__device__ float g_kvbias[256];
__device__ int   g_cntA [kB * kEA];
__device__ int   g_listA[kB * kEA * kS];
__device__ float g_gateA[kB * kEA * kS];
__device__ int2   g_slotA[kBS];
__device__ float2 g_gtokA[kBS];
__device__ float g_qg  [(size_t)kB * kEA * kS * kHD];
__device__ int   g_cntF [kEF];
__device__ int   g_listF[kEF * kBS];
__device__ float g_gateF[kEF * kBS];
__device__ int2   g_slotF[kBS];
__device__ float2 g_gtokF[kBS];
// partial outputs (atomic-free scatter)
__device__ float g_oPart [(size_t)kB * kEA * kS * kD];    // 134 MB
__device__ float g_f2Part[(size_t)kEF * kBS * kD];        // 268 MB
// bf16 hi/lo split activation buffers
__device__ __nv_bfloat16 g_xn1h[(size_t)kBS * kD];
__device__ __nv_bfloat16 g_xn1l[(size_t)kBS * kD];
__device__ __nv_bfloat16 g_xn2h[(size_t)kBS * kD];
__device__ __nv_bfloat16 g_xn2l[(size_t)kBS * kD];
__device__ __nv_bfloat16 g_ctxh[(size_t)kB * kEA * kS * kHD];
__device__ __nv_bfloat16 g_ctxl[(size_t)kB * kEA * kS * kHD];
__device__ __nv_bfloat16 g_hh [(size_t)kEF * kBS * kFH];
__device__ __nv_bfloat16 g_hl [(size_t)kEF * kBS * kFH];
// bf16 hi/lo transposed weights
__device__ __nv_bfloat16 g_w1th[(size_t)kEF * kFH * kD];
__device__ __nv_bfloat16 g_w1tl[(size_t)kEF * kFH * kD];
__device__ __nv_bfloat16 g_w2th[(size_t)kEF * kD * kFH];
__device__ __nv_bfloat16 g_w2tl[(size_t)kEF * kD * kFH];
__device__ __nv_bfloat16 g_qwth[(size_t)kEA * kHD * kD];
__device__ __nv_bfloat16 g_qwtl[(size_t)kEA * kHD * kD];
__device__ __nv_bfloat16 g_owth[(size_t)kEA * kD * kHD];
__device__ __nv_bfloat16 g_owtl[(size_t)kEA * kD * kHD];
__device__ __nv_bfloat16 g_kvth[(size_t)256 * kD];
__device__ __nv_bfloat16 g_kvtl[(size_t)256 * kD];

// ---------------- small utility kernels ----------------
__global__ void zero_cnts_kernel() {
    int i = threadIdx.x;
    if (i < kB * kEA) g_cntA[i] = 0;
    if (i < kEF)      g_cntF[i] = 0;
}

__global__ void pack_kvbias_kernel(const float* __restrict__ kb, const float* __restrict__ vb) {
    int i = threadIdx.x;
    g_kvbias[i] = (i < 128) ? kb[i] : vb[i - 128];
}

// final combine: out[t] += g0*part[s0] + g1*part[s1]
__global__ __launch_bounds__(256)
void combine_kernel(const float* __restrict__ part,
                    const int2* __restrict__ slot,
                    const float2* __restrict__ gate,
                    float* __restrict__ out)
{
    int t = blockIdx.x;
    int2 s = slot[t];
    float2 gv = gate[t];
    const float4* p0 = (const float4*)(part + (size_t)s.x * kD);
    const float4* p1 = (const float4*)(part + (size_t)s.y * kD);
    float4* o = (float4*)(out + (size_t)t * kD);
    for (int i = threadIdx.x; i < kD / 4; i += 256) {
        float4 a = o[i], b = p0[i], c = p1[i];
        a.x += gv.x * b.x + gv.y * c.x;
        a.y += gv.x * b.y + gv.y * c.y;
        a.z += gv.x * b.z + gv.y * c.z;
        a.w += gv.x * b.w + gv.y * c.w;
        o[i] = a;
    }
}

// ---------------- merged weight transpose+split (one launch) ----------------
__global__ __launch_bounds__(256)
void transp_all_kernel(const float* __restrict__ w1, const float* __restrict__ w2,
                       const float* __restrict__ qw, const float* __restrict__ ow,
                       const float* __restrict__ kw, const float* __restrict__ vw)
{
    int bid = blockIdx.x;
    const float* in; __nv_bfloat16* oh; __nv_bfloat16* ol;
    int K, N, e, r;
    if (bid < 8192)       { in = w1; oh = g_w1th; ol = g_w1tl; K = kD;  N = kFH; e = bid >> 9; r = bid & 511; }
    else if (bid < 16384) { bid -= 8192;  in = w2; oh = g_w2th; ol = g_w2tl; K = kFH; N = kD;  e = bid >> 9; r = bid & 511; }
    else if (bid < 17408) { bid -= 16384; in = qw; oh = g_qwth; ol = g_qwtl; K = kD;  N = kHD; e = bid >> 7; r = bid & 127; }
    else if (bid < 18432) { bid -= 17408; in = ow; oh = g_owth; ol = g_owtl; K = kHD; N = kD;  e = bid >> 7; r = bid & 127; }
    else if (bid < 18560) { bid -= 18432; in = kw; oh = g_kvth; ol = g_kvtl; K = kD;  N = kHD; e = 0; r = bid; }
    else                  { bid -= 18560; in = vw; oh = g_kvth + (size_t)128 * kD;
                            ol = g_kvtl + (size_t)128 * kD; K = kD; N = kHD; e = 0; r = bid; }
    int nT = N >> 5;
    int nb = (r % nT) * 32, kb = (r / nT) * 32;

    __shared__ float t[32][33];
    int tx = threadIdx.x & 31, ty = threadIdx.x >> 5;
    const float* ie = in + (size_t)e * K * N;
    for (int i = ty; i < 32; i += 8)
        t[i][tx] = ie[(size_t)(kb + i) * N + nb + tx];
    __syncthreads();
    size_t ob = (size_t)e * N * K;
    for (int j = ty; j < 32; j += 8) {
        float v = t[tx][j];
        __nv_bfloat16 h = __float2bfloat16(v);
        size_t o = ob + (size_t)(nb + j) * K + kb + tx;
        oh[o] = h;
        ol[o] = __float2bfloat16(v - __bfloat162float(h));
    }
}

// ---------------- fused LayerNorm + optional combine + top-2 router ----------------
// COMBINE: x_t = x[t] + g0*part[s0] + g1*part[s1]  (attention residual merge)
template <int E, bool COMBINE>
__global__ __launch_bounds__(256)
void ln_gate_kernel(const float* __restrict__ x,
                    const float* __restrict__ w,
                    const float* __restrict__ bvec,
                    const float* __restrict__ gw,   // [D, E] row-major
                    __nv_bfloat16* __restrict__ xnh,
                    __nv_bfloat16* __restrict__ xnl,
                    float* __restrict__ resid,      // residual base out, may be null
                    const float* __restrict__ part,
                    const int2* __restrict__ slotIn,
                    const float2* __restrict__ gateIn,
                    int* __restrict__ cnt,
                    int* __restrict__ list,
                    float* __restrict__ gates,
                    int2* __restrict__ slotOut,
                    float2* __restrict__ gateOut,
                    int cap, int perBatch)
{
    __shared__ __align__(16) float xs[kD];
    __shared__ float red1[8], red2[8];
    __shared__ float lred[8][E];
    __shared__ float s_mu, s_rstd;

    int t    = blockIdx.x;
    int tid  = threadIdx.x;
    int lane = tid & 31, wid = tid >> 5;

    const float4* xin = (const float4*)(x + (size_t)t * kD);
    float4* xs4 = (float4*)xs;
    float4* rout = resid ? (float4*)(resid + (size_t)t * kD) : nullptr;
    const float4* p0 = nullptr; const float4* p1 = nullptr;
    float2 gA = make_float2(0.f, 0.f);
    if (COMBINE) {
        int2 sA = slotIn[t];
        gA = gateIn[t];
        p0 = (const float4*)(part + (size_t)sA.x * kD);
        p1 = (const float4*)(part + (size_t)sA.y * kD);
    }
    float s = 0.f, ss = 0.f;
    for (int i = tid; i < kD / 4; i += 256) {
        float4 v = xin[i];
        if (COMBINE) {
            float4 a = p0[i], b = p1[i];
            v.x += gA.x * a.x + gA.y * b.x;
            v.y += gA.x * a.y + gA.y * b.y;
            v.z += gA.x * a.z + gA.y * b.z;
            v.w += gA.x * a.w + gA.y * b.w;
        }
        xs4[i] = v;
        if (rout) rout[i] = v;
        s  += v.x + v.y + v.z + v.w;
        ss += v.x * v.x + v.y * v.y + v.z * v.z + v.w * v.w;
    }
    #pragma unroll
    for (int o = 16; o; o >>= 1) {
        s  += __shfl_xor_sync(~0u, s, o);
        ss += __shfl_xor_sync(~0u, ss, o);
    }
    if (lane == 0) { red1[wid] = s; red2[wid] = ss; }
    __syncthreads();
    if (tid == 0) {
        float S1 = 0.f, S2 = 0.f;
        #pragma unroll
        for (int i = 0; i < 8; i++) { S1 += red1[i]; S2 += red2[i]; }
        float mu  = S1 / kD;
        float var = S2 / kD - mu * mu;
        s_mu = mu; s_rstd = rsqrtf(var + kEPS);
    }
    __syncthreads();
    float mu = s_mu, rstd = s_rstd;
    for (int i = tid; i < kD / 2; i += 256) {
        float v0 = (xs[2 * i]     - mu) * rstd * w[2 * i]     + bvec[2 * i];
        float v1 = (xs[2 * i + 1] - mu) * rstd * w[2 * i + 1] + bvec[2 * i + 1];
        xs[2 * i] = v0; xs[2 * i + 1] = v1;
        __nv_bfloat16 h0 = __float2bfloat16(v0);
        __nv_bfloat16 h1 = __float2bfloat16(v1);
        __nv_bfloat162 H; H.x = h0; H.y = h1;
        __nv_bfloat162 L;
        L.x = __float2bfloat16(v0 - __bfloat162float(h0));
        L.y = __float2bfloat16(v1 - __bfloat162float(h1));
        ((__nv_bfloat162*)(xnh + (size_t)t * kD))[i] = H;
        ((__nv_bfloat162*)(xnl + (size_t)t * kD))[i] = L;
    }
    __syncthreads();

    // router logits: coalesced gw rows, register accumulators
    float accE[E];
    #pragma unroll
    for (int e = 0; e < E; e++) accE[e] = 0.f;
    #pragma unroll
    for (int j = 0; j < 4; j++) {
        int d = tid + 256 * j;
        float xv = xs[d];
        const float4* gp = (const float4*)(gw + (size_t)d * E);
        #pragma unroll
        for (int q = 0; q < E / 4; q++) {
            float4 gv = gp[q];
            accE[4 * q + 0] += xv * gv.x;
            accE[4 * q + 1] += xv * gv.y;
            accE[4 * q + 2] += xv * gv.z;
            accE[4 * q + 3] += xv * gv.w;
        }
    }
    #pragma unroll
    for (int e = 0; e < E; e++)
        #pragma unroll
        for (int o = 16; o; o >>= 1) accE[e] += __shfl_xor_sync(~0u, accE[e], o);
    if (lane == 0) {
        #pragma unroll
        for (int e = 0; e < E; e++) lred[wid][e] = accE[e];
    }
    __syncthreads();

    if (tid == 0) {
        float logits[E];
        #pragma unroll
        for (int e = 0; e < E; e++) {
            float a = 0.f;
            #pragma unroll
            for (int i = 0; i < 8; i++) a += lred[i][e];
            logits[e] = a;
        }
        int e0 = 0; float v0 = logits[0];
        #pragma unroll
        for (int e = 1; e < E; e++) if (logits[e] > v0) { v0 = logits[e]; e0 = e; }
        int e1 = -1; float v1 = -3.4e38f;
        #pragma unroll
        for (int e = 0; e < E; e++) {
            if (e == e0) continue;
            if (logits[e] > v1) { v1 = logits[e]; e1 = e; }
        }
        float a1  = __expf(v1 - v0);
        float inv = 1.f / (1.f + a1);
        float g0 = inv, g1 = a1 * inv;
        int bb = perBatch ? (t / kS) : 0;
        int grp0 = bb * E + e0;
        int p0i = atomicAdd(&cnt[grp0], 1);
        list[grp0 * cap + p0i] = t; gates[grp0 * cap + p0i] = g0;
        int grp1 = bb * E + e1;
        int p1i = atomicAdd(&cnt[grp1], 1);
        list[grp1 * cap + p1i] = t; gates[grp1 * cap + p1i] = g1;
        slotOut[t] = make_int2(grp0 * cap + p0i, grp1 * cap + p1i);
        gateOut[t] = make_float2(g0, g1);
    }
}

// ---------------- packed f32x2 helpers ----------------
__device__ __forceinline__ void fma2(ull& d, ull a, ull b) {
    asm("fma.rn.f32x2 %0, %1, %2, %0;" : "+l"(d) : "l"(a), "l"(b));
}
__device__ __forceinline__ void mul2(ull& d, ull a, ull b) {
    asm("mul.rn.f32x2 %0, %1, %2;" : "=l"(d) : "l"(a), "l"(b));
}
__device__ __forceinline__ ull pack_dup(float a) {
    ull r;
    asm("mov.b64 %0, {%1, %1};" : "=l"(r) : "f"(a));
    return r;
}
__device__ __forceinline__ float2 unpack2(ull v) {
    float2 r;
    asm("mov.b64 {%0, %1}, %2;" : "=f"(r.x), "=f"(r.y) : "l"(v));
    return r;
}

// ---------------- warp-MMA (HMMA bf16) + ldmatrix ----------------
__device__ __forceinline__ void mma16816(float* c, const unsigned* a, const unsigned* b) {
    asm volatile(
        "mma.sync.aligned.m16n8k16.row.col.f32.bf16.bf16.f32 "
        "{%0,%1,%2,%3}, {%4,%5,%6,%7}, {%8,%9}, {%0,%1,%2,%3};"
        : "+f"(c[0]), "+f"(c[1]), "+f"(c[2]), "+f"(c[3])
        : "r"(a[0]), "r"(a[1]), "r"(a[2]), "r"(a[3]), "r"(b[0]), "r"(b[1]));
}
__device__ __forceinline__ void ldmx4(unsigned* r, unsigned addr) {
    asm volatile("ldmatrix.sync.aligned.m8n8.x4.shared.b16 {%0,%1,%2,%3}, [%4];"
                 : "=r"(r[0]), "=r"(r[1]), "=r"(r[2]), "=r"(r[3]) : "r"(addr));
}
__device__ __forceinline__ unsigned smem_u32(const void* p) {
    unsigned a;
    asm("{ .reg .u64 t; cvta.to.shared.u64 t, %1; cvt.u32.u64 %0, t; }" : "=r"(a) : "l"(p));
    return a;
}

// ---------------- generic grouped HMMA GEMM (ldmatrix fragments) ----------------
// OMODE 0: out f32 at grouped/dense rows, val=(acc+bias)*alpha
// OMODE 1: relu(acc+bias) -> bf16 hi/lo at grouped rows
template <int OMODE, bool GATHER_A, bool DENSE>
__global__ __launch_bounds__(256)
void wmma_gemm_kernel(const __nv_bfloat16* __restrict__ Ah,
                      const __nv_bfloat16* __restrict__ Al,
                      const __nv_bfloat16* __restrict__ Bh,   // [E][N][K]
                      const __nv_bfloat16* __restrict__ Bl,
                      const float* __restrict__ bias,         // [E][N]
                      float* __restrict__ outF,
                      __nv_bfloat16* __restrict__ outH,
                      __nv_bfloat16* __restrict__ outL,
                      const int* __restrict__ list,
                      const int* __restrict__ cnt,
                      int Mfixed, int N, int K, int cap, int wMod, float alpha)
{
    int g = blockIdx.z;
    int M = DENSE ? Mfixed : cnt[g];
    int e = DENSE ? 0 : (g % wMod);
    int row0 = blockIdx.x * 128;
    if (row0 >= M) return;
    int col0 = blockIdx.y * 128;

    extern __shared__ __align__(16) __nv_bfloat16 sm[];
    __shared__ int rowTok[128];

    int tid  = threadIdx.x;
    int wid  = tid >> 5;
    int lane = tid & 31;
    int gq   = lane >> 2;
    int tq   = lane & 3;

    if (GATHER_A && tid < 128) {
        int r = row0 + tid;
        rowTok[tid] = (r < M) ? list[(size_t)g * cap + r] : 0;
    }
    __syncthreads();

    auto tilep = [&](int buf, int t) -> __nv_bfloat16* {
        return sm + ((size_t)(buf * 4 + t)) * (128 * kPAD);
    };
    unsigned smBase = smem_u32(sm);
    auto tileu = [&](int buf, int t) -> unsigned {
        return smBase + (unsigned)((buf * 4 + t) * (128 * kPAD) * 2);
    };

    auto loadChunk = [&](int c, int buf) {
        int k0 = c * 32;
        #pragma unroll
        for (int i = 0; i < 2; i++) {
            int idx = tid + 256 * i;
            int r   = idx >> 2;
            int u   = idx & 3;
            uint4 vh = make_uint4(0, 0, 0, 0), vl = make_uint4(0, 0, 0, 0);
            int gr = row0 + r;
            if (gr < M) {
                size_t ar;
                if (GATHER_A)   ar = (size_t)rowTok[r];
                else if (DENSE) ar = (size_t)gr;
                else            ar = (size_t)g * cap + gr;
                vh = *(const uint4*)(Ah + ar * K + k0 + u * 8);
                vl = *(const uint4*)(Al + ar * K + k0 + u * 8);
            }
            *(uint4*)(tilep(buf, 0) + r * kPAD + u * 8) = vh;
            *(uint4*)(tilep(buf, 1) + r * kPAD + u * 8) = vl;
            size_t br = (size_t)e * N + col0 + r;
            uint4 bh = *(const uint4*)(Bh + br * K + k0 + u * 8);
            uint4 bl = *(const uint4*)(Bl + br * K + k0 + u * 8);
            *(uint4*)(tilep(buf, 2) + r * kPAD + u * 8) = bh;
            *(uint4*)(tilep(buf, 3) + r * kPAD + u * 8) = bl;
        }
    };

    float acc[4][4][4];
    #pragma unroll
    for (int mf = 0; mf < 4; mf++)
        #pragma unroll
        for (int nf = 0; nf < 4; nf++)
            #pragma unroll
            for (int q = 0; q < 4; q++) acc[mf][nf][q] = 0.f;

    int warpM = (wid & 1) * 64;
    int warpN = (wid >> 1) * 32;
    int T = K >> 5;

    int rowA = (lane & 7) + ((lane >> 3) & 1) * 8;
    int kA   = ((lane >> 4) & 1) * 8;
    int rowB = (lane & 7) + ((lane >> 4) & 1) * 8;
    int kB   = ((lane >> 3) & 1) * 8;

    loadChunk(0, 0);
    __syncthreads();

    for (int c = 0; c < T; c++) {
        int buf = c & 1;
        if (c + 1 < T) loadChunk(c + 1, buf ^ 1);

        unsigned uAh = tileu(buf, 0), uAl = tileu(buf, 1);
        unsigned uBh = tileu(buf, 2), uBl = tileu(buf, 3);

        #pragma unroll
        for (int ks = 0; ks < 2; ks++) {
            int k0 = ks * 16;
            unsigned ah[4][4], al[4][4], bh[2][4], bl[2][4];
            #pragma unroll
            for (int mf = 0; mf < 4; mf++) {
                unsigned off = (unsigned)(((warpM + mf * 16 + rowA) * kPAD + k0 + kA) * 2);
                ldmx4(ah[mf], uAh + off);
                ldmx4(al[mf], uAl + off);
            }
            #pragma unroll
            for (int np = 0; np < 2; np++) {
                unsigned off = (unsigned)(((warpN + np * 16 + rowB) * kPAD + k0 + kB) * 2);
                ldmx4(bh[np], uBh + off);
                ldmx4(bl[np], uBl + off);
            }
            #pragma unroll
            for (int mf = 0; mf < 4; mf++)
                #pragma unroll
                for (int nf = 0; nf < 4; nf++) {
                    const unsigned* bhf = &bh[nf >> 1][(nf & 1) * 2];
                    const unsigned* blf = &bl[nf >> 1][(nf & 1) * 2];
                    mma16816(acc[mf][nf], ah[mf], bhf);
                    mma16816(acc[mf][nf], ah[mf], blf);
                    mma16816(acc[mf][nf], al[mf], bhf);
                }
        }
        __syncthreads();
    }

    // ---- epilogue ----
    const float* bg = bias + (size_t)e * N;
    #pragma unroll
    for (int mf = 0; mf < 4; mf++) {
        #pragma unroll
        for (int half = 0; half < 2; half++) {
            int rloc = warpM + mf * 16 + gq + half * 8;
            int gr   = row0 + rloc;
            if (gr >= M) continue;
            #pragma unroll
            for (int nf = 0; nf < 4; nf++) {
                int ncol = col0 + warpN + nf * 8 + 2 * tq;
                float v0 = acc[mf][nf][half * 2 + 0] + bg[ncol];
                float v1 = acc[mf][nf][half * 2 + 1] + bg[ncol + 1];
                if (OMODE == 0) {
                    size_t orow = DENSE ? (size_t)gr : (size_t)g * cap + gr;
                    float2 v; v.x = v0 * alpha; v.y = v1 * alpha;
                    *(float2*)(outF + orow * N + ncol) = v;
                } else {
                    v0 = fmaxf(v0, 0.f);
                    v1 = fmaxf(v1, 0.f);
                    __nv_bfloat16 h0 = __float2bfloat16(v0);
                    __nv_bfloat16 h1 = __float2bfloat16(v1);
                    __nv_bfloat162 H; H.x = h0; H.y = h1;
                    __nv_bfloat162 L;
                    L.x = __float2bfloat16(v0 - __bfloat162float(h0));
                    L.y = __float2bfloat16(v1 - __bfloat162float(h1));
                    size_t off = ((size_t)g * cap + gr) * N + ncol;
                    *(__nv_bfloat162*)(outH + off) = H;
                    *(__nv_bfloat162*)(outL + off) = L;
                }
            }
        }
    }
}

// ---------------- routed attention core (QT=32, KT=64, 512 threads, f32x2) ----------------
namespace {
constexpr int QT    = 32;
constexpr int KT2   = 64;
constexpr int KPADF = 132;
constexpr int OFF_QS   = 0;
constexpr int OFF_RELQ = OFF_QS + QT * kHD;
constexpr int OFF_KS   = OFF_RELQ + QT * KPADF;
constexpr int OFF_VS   = OFF_KS + KT2 * KPADF;
constexpr int OFF_PS   = OFF_VS + KT2 * KPADF;
constexpr int OFF_QPOS = OFF_PS + QT * KT2;
constexpr int ATTN_SMEM_BYTES = (OFF_QPOS + QT) * 4;   // ~109 KB
}

__global__ __launch_bounds__(512)
void attn_kernel(const float* __restrict__ rel_table,
                 __nv_bfloat16* __restrict__ ctxh,
                 __nv_bfloat16* __restrict__ ctxl)
{
    extern __shared__ __align__(16) float smf[];
    float* qs   = smf + OFF_QS;
    float* relq = smf + OFF_RELQ;
    float* ks   = smf + OFF_KS;
    float* vs   = smf + OFF_VS;
    float* ps   = smf + OFF_PS;
    int*   qpos = (int*)(smf + OFF_QPOS);

    int g  = blockIdx.x;
    int b  = g / kEA;
    int qt = blockIdx.y;
    int cnt  = g_cntA[g];
    int base = qt * QT;
    if (base >= cnt) return;

    int tid = threadIdx.x;

    for (int i = tid; i < QT * kHD / 4; i += 512) {
        int qi = i >> 5, h4 = i & 31;
        float4 v = make_float4(0.f, 0.f, 0.f, 0.f);
        if (base + qi < cnt)
            v = ((const float4*)&g_qg[((size_t)g * kS + base + qi) * kHD])[h4];
        ((float4*)(qs + qi * kHD))[h4] = v;
    }
    if (tid < QT) {
        int t = (base + tid < cnt) ? g_listA[g * kS + base + tid] : 0;
        qpos[tid] = t & (kS - 1);
    }
    __syncthreads();

    for (int idx = tid; idx < QT * kR; idx += 512) {
        int qi = idx / kR, r = idx % kR;
        const float4* q4 = (const float4*)(qs + qi * kHD);
        const float4* t4 = (const float4*)&rel_table[(size_t)r * kHD];
        float s = 0.f;
        #pragma unroll
        for (int h = 0; h < kHD / 4; h++) {
            float4 a = q4[h], c = t4[h];
            s += a.x * c.x + a.y * c.y + a.z * c.z + a.w * c.w;
        }
        relq[qi * KPADF + r] = s;
    }
    __syncthreads();

    int qi = tid >> 4;
    int li = tid & 15;
    float m = -1e30f, l = 0.f;
    ull acc2[4];
    #pragma unroll
    for (int t = 0; t < 4; t++) acc2[t] = 0ull;
    int myq = qpos[qi];
    const float4* q4 = (const float4*)(qs + qi * kHD);

    for (int c0 = 0; c0 < kS; c0 += KT2) {
        for (int i = tid; i < KT2 * 64; i += 512) {
            int kk = i >> 6, h4 = i & 63;
            float4 v = ((const float4*)&g_kvbuf[((size_t)b * kS + c0 + kk) * 256])[h4];
            if (h4 < 32) ((float4*)(ks + kk * KPADF))[h4] = v;
            else         ((float4*)(vs + kk * KPADF))[h4 - 32] = v;
        }
        __syncthreads();

        float sv[4];
        #pragma unroll
        for (int t4 = 0; t4 < 4; t4++) {
            int key = li + 16 * t4;
            const float4* k4 = (const float4*)(ks + key * KPADF);
            ull s2a = 0ull, s2b = 0ull;
            #pragma unroll
            for (int h = 0; h < kHD / 4; h++) {
                float4 a = q4[h], kv = k4[h];
                fma2(s2a, ((const ull*)&a)[0], ((const ull*)&kv)[0]);
                fma2(s2b, ((const ull*)&a)[1], ((const ull*)&kv)[1]);
            }
            float2 r1 = unpack2(s2a), r2 = unpack2(s2b);
            float s = r1.x + r1.y + r2.x + r2.y;
            int rel = c0 + key - myq;
            rel = min(max(rel, -kMAXP), kMAXP) + kMAXP;
            sv[t4] = s + relq[qi * KPADF + rel];
        }

        float cm = fmaxf(fmaxf(sv[0], sv[1]), fmaxf(sv[2], sv[3]));
        #pragma unroll
        for (int o = 8; o; o >>= 1) cm = fmaxf(cm, __shfl_xor_sync(~0u, cm, o));
        float mn = fmaxf(m, cm);
        float scale = __expf(m - mn);
        float p0 = __expf(sv[0] - mn), p1 = __expf(sv[1] - mn);
        float p2 = __expf(sv[2] - mn), p3 = __expf(sv[3] - mn);
        float psum = p0 + p1 + p2 + p3;
        #pragma unroll
        for (int o = 8; o; o >>= 1) psum += __shfl_xor_sync(~0u, psum, o);
        l = l * scale + psum;
        m = mn;
        ps[qi * KT2 + li]      = p0;
        ps[qi * KT2 + li + 16] = p1;
        ps[qi * KT2 + li + 32] = p2;
        ps[qi * KT2 + li + 48] = p3;
        __syncwarp();

        ull sc2 = pack_dup(scale);
        #pragma unroll
        for (int t = 0; t < 4; t++) mul2(acc2[t], acc2[t], sc2);
        #pragma unroll
        for (int kk = 0; kk < KT2; kk++) {
            ull pv = pack_dup(ps[qi * KT2 + kk]);
            const ull* v2 = (const ull*)(vs + kk * KPADF + li * 8);
            fma2(acc2[0], pv, v2[0]);
            fma2(acc2[1], pv, v2[1]);
            fma2(acc2[2], pv, v2[2]);
            fma2(acc2[3], pv, v2[3]);
        }
        __syncthreads();
    }

    if (base + qi < cnt) {
        float inv = 1.f / l;
        size_t off = ((size_t)g * kS + base + qi) * kHD + li * 8;
        #pragma unroll
        for (int t = 0; t < 4; t++) {
            float2 v = unpack2(acc2[t]);
            float v0 = v.x * inv, v1 = v.y * inv;
            __nv_bfloat16 h0 = __float2bfloat16(v0);
            __nv_bfloat16 h1 = __float2bfloat16(v1);
            __nv_bfloat162 H; H.x = h0; H.y = h1;
            __nv_bfloat162 L;
            L.x = __float2bfloat16(v0 - __bfloat162float(h0));
            L.y = __float2bfloat16(v1 - __bfloat162float(h1));
            *(__nv_bfloat162*)(ctxh + off + 2 * t) = H;
            *(__nv_bfloat162*)(ctxl + off + 2 * t) = L;
        }
    }
}

// ---------------- launch ----------------
extern "C" void kernel_launch(void* const* d_in, const int* in_sizes, int n_in,
                              void* d_out, int out_size)
{
    const float* src   = (const float*)d_in[0];
    const float* ln1_w = (const float*)d_in[1];
    const float* ln1_b = (const float*)d_in[2];
    const float* ln2_w = (const float*)d_in[3];
    const float* ln2_b = (const float*)d_in[4];
    const float* agw   = (const float*)d_in[5];
    const float* q_w   = (const float*)d_in[6];
    const float* q_b   = (const float*)d_in[7];
    const float* k_w   = (const float*)d_in[8];
    const float* k_b   = (const float*)d_in[9];
    const float* v_w   = (const float*)d_in[10];
    const float* v_b   = (const float*)d_in[11];
    const float* o_w   = (const float*)d_in[12];
    const float* o_b   = (const float*)d_in[13];
    const float* rel   = (const float*)d_in[14];
    const float* fgw   = (const float*)d_in[15];
    const float* w1    = (const float*)d_in[16];
    const float* b1    = (const float*)d_in[17];
    const float* w2    = (const float*)d_in[18];
    const float* b2    = (const float*)d_in[19];
    float* out = (float*)d_out;

    float *kvb, *kvbias, *qg, *gateA, *gateF, *oPart, *f2Part;
    int *cntA, *listA, *cntF, *listF;
    int2 *slotA, *slotF; float2 *gtokA, *gtokF;
    __nv_bfloat16 *xn1h, *xn1l, *xn2h, *xn2l, *ctxh, *ctxl, *hh, *hl;
    __nv_bfloat16 *w1th, *w1tl, *w2th, *w2tl, *qwth, *qwtl, *owth, *owtl, *kvth, *kvtl;
    cudaGetSymbolAddress((void**)&kvb,    g_kvbuf);
    cudaGetSymbolAddress((void**)&kvbias, g_kvbias);
    cudaGetSymbolAddress((void**)&qg,     g_qg);
    cudaGetSymbolAddress((void**)&gateA,  g_gateA);
    cudaGetSymbolAddress((void**)&gateF,  g_gateF);
    cudaGetSymbolAddress((void**)&cntA,   g_cntA);
    cudaGetSymbolAddress((void**)&listA,  g_listA);
    cudaGetSymbolAddress((void**)&cntF,   g_cntF);
    cudaGetSymbolAddress((void**)&listF,  g_listF);
    cudaGetSymbolAddress((void**)&slotA,  g_slotA);
    cudaGetSymbolAddress((void**)&slotF,  g_slotF);
    cudaGetSymbolAddress((void**)&gtokA,  g_gtokA);
    cudaGetSymbolAddress((void**)&gtokF,  g_gtokF);
    cudaGetSymbolAddress((void**)&oPart,  g_oPart);
    cudaGetSymbolAddress((void**)&f2Part, g_f2Part);
    cudaGetSymbolAddress((void**)&xn1h,   g_xn1h);
    cudaGetSymbolAddress((void**)&xn1l,   g_xn1l);
    cudaGetSymbolAddress((void**)&xn2h,   g_xn2h);
    cudaGetSymbolAddress((void**)&xn2l,   g_xn2l);
    cudaGetSymbolAddress((void**)&ctxh,   g_ctxh);
    cudaGetSymbolAddress((void**)&ctxl,   g_ctxl);
    cudaGetSymbolAddress((void**)&hh,     g_hh);
    cudaGetSymbolAddress((void**)&hl,     g_hl);
    cudaGetSymbolAddress((void**)&w1th,   g_w1th);
    cudaGetSymbolAddress((void**)&w1tl,   g_w1tl);
    cudaGetSymbolAddress((void**)&w2th,   g_w2th);
    cudaGetSymbolAddress((void**)&w2tl,   g_w2tl);
    cudaGetSymbolAddress((void**)&qwth,   g_qwth);
    cudaGetSymbolAddress((void**)&qwtl,   g_qwtl);
    cudaGetSymbolAddress((void**)&owth,   g_owth);
    cudaGetSymbolAddress((void**)&owtl,   g_owtl);
    cudaGetSymbolAddress((void**)&kvth,   g_kvth);
    cudaGetSymbolAddress((void**)&kvtl,   g_kvtl);

    constexpr int kWmmaSmem = 2 * 4 * 128 * kPAD * 2;   // 81920
    cudaFuncSetAttribute(wmma_gemm_kernel<0, true,  false>,
                         cudaFuncAttributeMaxDynamicSharedMemorySize, kWmmaSmem);
    cudaFuncSetAttribute(wmma_gemm_kernel<0, false, true>,
                         cudaFuncAttributeMaxDynamicSharedMemorySize, kWmmaSmem);
    cudaFuncSetAttribute(wmma_gemm_kernel<0, false, false>,
                         cudaFuncAttributeMaxDynamicSharedMemorySize, kWmmaSmem);
    cudaFuncSetAttribute(wmma_gemm_kernel<1, true,  false>,
                         cudaFuncAttributeMaxDynamicSharedMemorySize, kWmmaSmem);
    cudaFuncSetAttribute(attn_kernel,
                         cudaFuncAttributeMaxDynamicSharedMemorySize, ATTN_SMEM_BYTES);

    zero_cnts_kernel<<<1, 64>>>();
    pack_kvbias_kernel<<<1, 256>>>(k_b, v_b);

    // ---- all weight transposes + splits in ONE launch ----
    transp_all_kernel<<<18688, 256>>>(w1, w2, q_w, o_w, k_w, v_w);

    // ---- LN1 + attention router (no residual copy needed) ----
    ln_gate_kernel<kEA, false><<<kBS, 256>>>(src, ln1_w, ln1_b, agw, xn1h, xn1l,
                                             nullptr, nullptr, nullptr, nullptr,
                                             cntA, listA, gateA, slotA, gtokA, kS, 1);

    // ---- fused k+v projection (dense, N=256) -> packed kv ----
    wmma_gemm_kernel<0, false, true><<<dim3(kBS / 128, 2, 1), 256, kWmmaSmem>>>(
        xn1h, xn1l, kvth, kvtl, kvbias, kvb, nullptr, nullptr,
        nullptr, nullptr, kBS, 256, kD, 0, 1, 1.f);

    // ---- routed q projection ----
    wmma_gemm_kernel<0, true, false><<<dim3(kS / 128, 1, kB * kEA), 256, kWmmaSmem>>>(
        xn1h, xn1l, qwth, qwtl, q_b, qg, nullptr, nullptr,
        listA, cntA, 0, kHD, kD, kS, kEA, kQScale);

    // ---- attention core (emits ctx bf16 hi/lo) ----
    attn_kernel<<<dim3(kB * kEA, kS / QT), 512, ATTN_SMEM_BYTES>>>(rel, ctxh, ctxl);

    // ---- o-projection: plain grouped stores into oPart (atomic-free) ----
    wmma_gemm_kernel<0, false, false><<<dim3(kS / 128, kD / 128, kB * kEA), 256, kWmmaSmem>>>(
        ctxh, ctxl, owth, owtl, o_b, oPart, nullptr, nullptr,
        nullptr, cntA, 0, kD, kHD, kS, kEA, 1.f);

    // ---- LN2 fused with attention combine (x = src + g0*oPart[s0] + g1*oPart[s1]) ----
    ln_gate_kernel<kEF, true><<<kBS, 256>>>(src, ln2_w, ln2_b, fgw, xn2h, xn2l,
                                            out, oPart, slotA, gtokA,
                                            cntF, listF, gateF, slotF, gtokF, kBS, 0);

    // ---- routed FFN up-proj + relu ----
    wmma_gemm_kernel<1, true, false><<<dim3(kBS / 128, kFH / 128, kEF), 256, kWmmaSmem>>>(
        xn2h, xn2l, w1th, w1tl, b1, nullptr, hh, hl,
        listF, cntF, 0, kFH, kD, kBS, kEF, 1.f);

    // ---- FFN down-proj: plain grouped stores into f2Part ----
    wmma_gemm_kernel<0, false, false><<<dim3(kBS / 128, kD / 128, kEF), 256, kWmmaSmem>>>(
        hh, hl, w2th, w2tl, b2, f2Part, nullptr, nullptr,
        nullptr, cntF, 0, kD, kFH, kBS, kEF, 1.f);

    // ---- final combine: out += g0*f2Part[s0] + g1*f2Part[s1] ----
    combine_kernel<<<kBS, 256>>>(f2Part, slotF, gtokF, out);
}

// round 15
// speedup vs baseline: 1.4538x; 1.4538x over previous
#include <cuda_runtime.h>
#include <cuda_bf16.h>

// ---------------- problem constants ----------------
namespace {
constexpr int kD    = 1024;
constexpr int kHD   = 128;
constexpr int kEA   = 8;
constexpr int kEF   = 16;
constexpr int kFH   = 512;
constexpr int kMAXP = 64;
constexpr int kR    = 2 * kMAXP + 1;   // 129
constexpr int kB    = 4;
constexpr int kS    = 1024;
constexpr int kBS   = kB * kS;         // 4096
constexpr float kEPS = 1e-5f;
constexpr float kQScale = 0.08838834764831845f;   // 128^-0.5
constexpr int kPAD = 40;               // smem row pitch in bf16 for wmma tiles
}

typedef unsigned long long ull;

// ---------------- device scratch (allocation-free) ----------------
__device__ float g_xcur[kBS * kD];
__device__ float g_kvbias[256];
__device__ int   g_cntA [kB * kEA];
__device__ int   g_listA[kB * kEA * kS];
__device__ float g_gateA[kB * kEA * kS];
__device__ float g_qg  [(size_t)kB * kEA * kS * kHD];
__device__ int   g_cntF [kEF];
__device__ int   g_listF[kEF * kBS];
__device__ float g_gateF[kEF * kBS];
// bf16 k rows + transposed v for tensorized attention
__device__ __nv_bfloat16 g_kbh[(size_t)kBS * kHD];
__device__ __nv_bfloat16 g_kbl[(size_t)kBS * kHD];
__device__ __nv_bfloat16 g_vTh[(size_t)kB * kHD * kS];   // [b][h][token]
__device__ __nv_bfloat16 g_vTl[(size_t)kB * kHD * kS];
// bf16 hi/lo split activation buffers
__device__ __nv_bfloat16 g_xn1h[(size_t)kBS * kD];
__device__ __nv_bfloat16 g_xn1l[(size_t)kBS * kD];
__device__ __nv_bfloat16 g_xn2h[(size_t)kBS * kD];
__device__ __nv_bfloat16 g_xn2l[(size_t)kBS * kD];
__device__ __nv_bfloat16 g_ctxh[(size_t)kB * kEA * kS * kHD];
__device__ __nv_bfloat16 g_ctxl[(size_t)kB * kEA * kS * kHD];
__device__ __nv_bfloat16 g_hh [(size_t)kEF * kBS * kFH];
__device__ __nv_bfloat16 g_hl [(size_t)kEF * kBS * kFH];
// bf16 hi/lo transposed weights
__device__ __nv_bfloat16 g_w1th[(size_t)kEF * kFH * kD];
__device__ __nv_bfloat16 g_w1tl[(size_t)kEF * kFH * kD];
__device__ __nv_bfloat16 g_w2th[(size_t)kEF * kD * kFH];
__device__ __nv_bfloat16 g_w2tl[(size_t)kEF * kD * kFH];
__device__ __nv_bfloat16 g_qwth[(size_t)kEA * kHD * kD];
__device__ __nv_bfloat16 g_qwtl[(size_t)kEA * kHD * kD];
__device__ __nv_bfloat16 g_owth[(size_t)kEA * kD * kHD];
__device__ __nv_bfloat16 g_owtl[(size_t)kEA * kD * kHD];
__device__ __nv_bfloat16 g_kvth[(size_t)256 * kD];
__device__ __nv_bfloat16 g_kvtl[(size_t)256 * kD];

// ---------------- small utility kernels ----------------
__global__ void zero_cnts_kernel() {
    int i = threadIdx.x;
    if (i < kB * kEA) g_cntA[i] = 0;
    if (i < kEF)      g_cntF[i] = 0;
}

__global__ void pack_kvbias_kernel(const float* __restrict__ kb, const float* __restrict__ vb) {
    int i = threadIdx.x;
    g_kvbias[i] = (i < 128) ? kb[i] : vb[i - 128];
}

// ---------------- merged weight transpose+split (one launch) ----------------
__global__ __launch_bounds__(256)
void transp_all_kernel(const float* __restrict__ w1, const float* __restrict__ w2,
                       const float* __restrict__ qw, const float* __restrict__ ow,
                       const float* __restrict__ kw, const float* __restrict__ vw)
{
    int bid = blockIdx.x;
    const float* in; __nv_bfloat16* oh; __nv_bfloat16* ol;
    int K, N, e, r;
    if (bid < 8192)       { in = w1; oh = g_w1th; ol = g_w1tl; K = kD;  N = kFH; e = bid >> 9; r = bid & 511; }
    else if (bid < 16384) { bid -= 8192;  in = w2; oh = g_w2th; ol = g_w2tl; K = kFH; N = kD;  e = bid >> 9; r = bid & 511; }
    else if (bid < 17408) { bid -= 16384; in = qw; oh = g_qwth; ol = g_qwtl; K = kD;  N = kHD; e = bid >> 7; r = bid & 127; }
    else if (bid < 18432) { bid -= 17408; in = ow; oh = g_owth; ol = g_owtl; K = kHD; N = kD;  e = bid >> 7; r = bid & 127; }
    else if (bid < 18560) { bid -= 18432; in = kw; oh = g_kvth; ol = g_kvtl; K = kD;  N = kHD; e = 0; r = bid; }
    else                  { bid -= 18560; in = vw; oh = g_kvth + (size_t)128 * kD;
                            ol = g_kvtl + (size_t)128 * kD; K = kD; N = kHD; e = 0; r = bid; }
    int nT = N >> 5;
    int nb = (r % nT) * 32, kb = (r / nT) * 32;

    __shared__ float t[32][33];
    int tx = threadIdx.x & 31, ty = threadIdx.x >> 5;
    const float* ie = in + (size_t)e * K * N;
    for (int i = ty; i < 32; i += 8)
        t[i][tx] = ie[(size_t)(kb + i) * N + nb + tx];
    __syncthreads();
    size_t ob = (size_t)e * N * K;
    for (int j = ty; j < 32; j += 8) {
        float v = t[tx][j];
        __nv_bfloat16 h = __float2bfloat16(v);
        size_t o = ob + (size_t)(nb + j) * K + kb + tx;
        oh[o] = h;
        ol[o] = __float2bfloat16(v - __bfloat162float(h));
    }
}

// ---------------- fused LayerNorm + residual-copy + top-2 router ----------------
template <int E>
__global__ __launch_bounds__(256)
void ln_gate_kernel(const float* __restrict__ x,
                    const float* __restrict__ w,
                    const float* __restrict__ bvec,
                    const float* __restrict__ gw,   // [D, E] row-major
                    __nv_bfloat16* __restrict__ xnh,
                    __nv_bfloat16* __restrict__ xnl,
                    float* __restrict__ resid,
                    int* __restrict__ cnt,
                    int* __restrict__ list,
                    float* __restrict__ gates,
                    int cap, int perBatch)
{
    __shared__ __align__(16) float xs[kD];
    __shared__ float red1[8], red2[8];
    __shared__ float lred[8][E];
    __shared__ float s_mu, s_rstd;

    int t    = blockIdx.x;
    int tid  = threadIdx.x;
    int lane = tid & 31, wid = tid >> 5;

    const float4* xin = (const float4*)(x + (size_t)t * kD);
    float4* xs4 = (float4*)xs;
    float4* rout = resid ? (float4*)(resid + (size_t)t * kD) : nullptr;
    float s = 0.f, ss = 0.f;
    for (int i = tid; i < kD / 4; i += 256) {
        float4 v = xin[i];
        xs4[i] = v;
        if (rout) rout[i] = v;
        s  += v.x + v.y + v.z + v.w;
        ss += v.x * v.x + v.y * v.y + v.z * v.z + v.w * v.w;
    }
    #pragma unroll
    for (int o = 16; o; o >>= 1) {
        s  += __shfl_xor_sync(~0u, s, o);
        ss += __shfl_xor_sync(~0u, ss, o);
    }
    if (lane == 0) { red1[wid] = s; red2[wid] = ss; }
    __syncthreads();
    if (tid == 0) {
        float S1 = 0.f, S2 = 0.f;
        #pragma unroll
        for (int i = 0; i < 8; i++) { S1 += red1[i]; S2 += red2[i]; }
        float mu  = S1 / kD;
        float var = S2 / kD - mu * mu;
        s_mu = mu; s_rstd = rsqrtf(var + kEPS);
    }
    __syncthreads();
    float mu = s_mu, rstd = s_rstd;
    for (int i = tid; i < kD / 2; i += 256) {
        float v0 = (xs[2 * i]     - mu) * rstd * w[2 * i]     + bvec[2 * i];
        float v1 = (xs[2 * i + 1] - mu) * rstd * w[2 * i + 1] + bvec[2 * i + 1];
        xs[2 * i] = v0; xs[2 * i + 1] = v1;
        __nv_bfloat16 h0 = __float2bfloat16(v0);
        __nv_bfloat16 h1 = __float2bfloat16(v1);
        __nv_bfloat162 H; H.x = h0; H.y = h1;
        __nv_bfloat162 L;
        L.x = __float2bfloat16(v0 - __bfloat162float(h0));
        L.y = __float2bfloat16(v1 - __bfloat162float(h1));
        ((__nv_bfloat162*)(xnh + (size_t)t * kD))[i] = H;
        ((__nv_bfloat162*)(xnl + (size_t)t * kD))[i] = L;
    }
    __syncthreads();

    float accE[E];
    #pragma unroll
    for (int e = 0; e < E; e++) accE[e] = 0.f;
    #pragma unroll
    for (int j = 0; j < 4; j++) {
        int d = tid + 256 * j;
        float xv = xs[d];
        const float4* gp = (const float4*)(gw + (size_t)d * E);
        #pragma unroll
        for (int q = 0; q < E / 4; q++) {
            float4 gv = gp[q];
            accE[4 * q + 0] += xv * gv.x;
            accE[4 * q + 1] += xv * gv.y;
            accE[4 * q + 2] += xv * gv.z;
            accE[4 * q + 3] += xv * gv.w;
        }
    }
    #pragma unroll
    for (int e = 0; e < E; e++)
        #pragma unroll
        for (int o = 16; o; o >>= 1) accE[e] += __shfl_xor_sync(~0u, accE[e], o);
    if (lane == 0) {
        #pragma unroll
        for (int e = 0; e < E; e++) lred[wid][e] = accE[e];
    }
    __syncthreads();

    if (tid == 0) {
        float logits[E];
        #pragma unroll
        for (int e = 0; e < E; e++) {
            float a = 0.f;
            #pragma unroll
            for (int i = 0; i < 8; i++) a += lred[i][e];
            logits[e] = a;
        }
        int e0 = 0; float v0 = logits[0];
        #pragma unroll
        for (int e = 1; e < E; e++) if (logits[e] > v0) { v0 = logits[e]; e0 = e; }
        int e1 = -1; float v1 = -3.4e38f;
        #pragma unroll
        for (int e = 0; e < E; e++) {
            if (e == e0) continue;
            if (logits[e] > v1) { v1 = logits[e]; e1 = e; }
        }
        float a1  = __expf(v1 - v0);
        float inv = 1.f / (1.f + a1);
        float g0 = inv, g1 = a1 * inv;
        int bb = perBatch ? (t / kS) : 0;
        int grp0 = bb * E + e0;
        int p0 = atomicAdd(&cnt[grp0], 1);
        list[grp0 * cap + p0] = t; gates[grp0 * cap + p0] = g0;
        int grp1 = bb * E + e1;
        int p1 = atomicAdd(&cnt[grp1], 1);
        list[grp1 * cap + p1] = t; gates[grp1 * cap + p1] = g1;
    }
}

// ---------------- warp-MMA (HMMA bf16) + ldmatrix ----------------
__device__ __forceinline__ void mma16816(float* c, const unsigned* a, const unsigned* b) {
    asm volatile(
        "mma.sync.aligned.m16n8k16.row.col.f32.bf16.bf16.f32 "
        "{%0,%1,%2,%3}, {%4,%5,%6,%7}, {%8,%9}, {%0,%1,%2,%3};"
        : "+f"(c[0]), "+f"(c[1]), "+f"(c[2]), "+f"(c[3])
        : "r"(a[0]), "r"(a[1]), "r"(a[2]), "r"(a[3]), "r"(b[0]), "r"(b[1]));
}
__device__ __forceinline__ void ldmx4(unsigned* r, unsigned addr) {
    asm volatile("ldmatrix.sync.aligned.m8n8.x4.shared.b16 {%0,%1,%2,%3}, [%4];"
                 : "=r"(r[0]), "=r"(r[1]), "=r"(r[2]), "=r"(r[3]) : "r"(addr));
}
__device__ __forceinline__ unsigned smem_u32(const void* p) {
    unsigned a;
    asm("{ .reg .u64 t; cvta.to.shared.u64 t, %1; cvt.u32.u64 %0, t; }" : "=r"(a) : "l"(p));
    return a;
}
__device__ __forceinline__ void bf16_split(float v, __nv_bfloat16& h, __nv_bfloat16& l) {
    h = __float2bfloat16(v);
    l = __float2bfloat16(v - __bfloat162float(h));
}

// ---------------- generic grouped HMMA GEMM (ldmatrix fragments) ----------------
// OMODE 0: out f32 at grouped/dense rows, val=(acc+bias)*alpha
// OMODE 1: relu(acc+bias) -> bf16 hi/lo at grouped rows
// OMODE 2: atomicAdd(outF[token], gate*(acc+bias))  (gated scatter)
// OMODE 4: kv special (dense): ncol<128 -> k rows bf16 hi/lo (outH/outL);
//          ncol>=128 -> vT[b][h][tok] bf16 hi/lo (outH2/outL2)
template <int OMODE, bool GATHER_A, bool DENSE>
__global__ __launch_bounds__(256)
void wmma_gemm_kernel(const __nv_bfloat16* __restrict__ Ah,
                      const __nv_bfloat16* __restrict__ Al,
                      const __nv_bfloat16* __restrict__ Bh,   // [E][N][K]
                      const __nv_bfloat16* __restrict__ Bl,
                      const float* __restrict__ bias,         // [E][N]
                      float* __restrict__ outF,
                      __nv_bfloat16* __restrict__ outH,
                      __nv_bfloat16* __restrict__ outL,
                      __nv_bfloat16* __restrict__ outH2,
                      __nv_bfloat16* __restrict__ outL2,
                      const int* __restrict__ list,
                      const float* __restrict__ gates,
                      const int* __restrict__ cnt,
                      int Mfixed, int N, int K, int cap, int wMod, float alpha)
{
    int g = blockIdx.z;
    int M = DENSE ? Mfixed : cnt[g];
    int e = DENSE ? 0 : (g % wMod);
    int row0 = blockIdx.x * 128;
    if (row0 >= M) return;
    int col0 = blockIdx.y * 128;

    extern __shared__ __align__(16) __nv_bfloat16 sm[];
    __shared__ int   rowTok[128];
    __shared__ float rowG[128];

    int tid  = threadIdx.x;
    int wid  = tid >> 5;
    int lane = tid & 31;
    int gq   = lane >> 2;
    int tq   = lane & 3;

    if (!DENSE && tid < 128) {
        int r = row0 + tid;
        rowTok[tid] = (r < M) ? list[(size_t)g * cap + r] : 0;
        rowG[tid]   = (r < M && gates) ? gates[(size_t)g * cap + r] : 0.f;
    }
    __syncthreads();

    auto tilep = [&](int buf, int t) -> __nv_bfloat16* {
        return sm + ((size_t)(buf * 4 + t)) * (128 * kPAD);
    };
    unsigned smBase = smem_u32(sm);
    auto tileu = [&](int buf, int t) -> unsigned {
        return smBase + (unsigned)((buf * 4 + t) * (128 * kPAD) * 2);
    };

    auto loadChunk = [&](int c, int buf) {
        int k0 = c * 32;
        #pragma unroll
        for (int i = 0; i < 2; i++) {
            int idx = tid + 256 * i;
            int r   = idx >> 2;
            int u   = idx & 3;
            uint4 vh = make_uint4(0, 0, 0, 0), vl = make_uint4(0, 0, 0, 0);
            int gr = row0 + r;
            if (gr < M) {
                size_t ar;
                if (GATHER_A)   ar = (size_t)rowTok[r];
                else if (DENSE) ar = (size_t)gr;
                else            ar = (size_t)g * cap + gr;
                vh = *(const uint4*)(Ah + ar * K + k0 + u * 8);
                vl = *(const uint4*)(Al + ar * K + k0 + u * 8);
            }
            *(uint4*)(tilep(buf, 0) + r * kPAD + u * 8) = vh;
            *(uint4*)(tilep(buf, 1) + r * kPAD + u * 8) = vl;
            size_t br = (size_t)e * N + col0 + r;
            uint4 bh = *(const uint4*)(Bh + br * K + k0 + u * 8);
            uint4 bl = *(const uint4*)(Bl + br * K + k0 + u * 8);
            *(uint4*)(tilep(buf, 2) + r * kPAD + u * 8) = bh;
            *(uint4*)(tilep(buf, 3) + r * kPAD + u * 8) = bl;
        }
    };

    float acc[4][4][4];
    #pragma unroll
    for (int mf = 0; mf < 4; mf++)
        #pragma unroll
        for (int nf = 0; nf < 4; nf++)
            #pragma unroll
            for (int q = 0; q < 4; q++) acc[mf][nf][q] = 0.f;

    int warpM = (wid & 1) * 64;
    int warpN = (wid >> 1) * 32;
    int T = K >> 5;

    int rowA = (lane & 7) + ((lane >> 3) & 1) * 8;
    int kA   = ((lane >> 4) & 1) * 8;
    int rowB = (lane & 7) + ((lane >> 4) & 1) * 8;
    int kB   = ((lane >> 3) & 1) * 8;

    loadChunk(0, 0);
    __syncthreads();

    for (int c = 0; c < T; c++) {
        int buf = c & 1;
        if (c + 1 < T) loadChunk(c + 1, buf ^ 1);

        unsigned uAh = tileu(buf, 0), uAl = tileu(buf, 1);
        unsigned uBh = tileu(buf, 2), uBl = tileu(buf, 3);

        #pragma unroll
        for (int ks = 0; ks < 2; ks++) {
            int k0 = ks * 16;
            unsigned ah[4][4], al[4][4], bh[2][4], bl[2][4];
            #pragma unroll
            for (int mf = 0; mf < 4; mf++) {
                unsigned off = (unsigned)(((warpM + mf * 16 + rowA) * kPAD + k0 + kA) * 2);
                ldmx4(ah[mf], uAh + off);
                ldmx4(al[mf], uAl + off);
            }
            #pragma unroll
            for (int np = 0; np < 2; np++) {
                unsigned off = (unsigned)(((warpN + np * 16 + rowB) * kPAD + k0 + kB) * 2);
                ldmx4(bh[np], uBh + off);
                ldmx4(bl[np], uBl + off);
            }
            #pragma unroll
            for (int mf = 0; mf < 4; mf++)
                #pragma unroll
                for (int nf = 0; nf < 4; nf++) {
                    const unsigned* bhf = &bh[nf >> 1][(nf & 1) * 2];
                    const unsigned* blf = &bl[nf >> 1][(nf & 1) * 2];
                    mma16816(acc[mf][nf], ah[mf], bhf);
                    mma16816(acc[mf][nf], ah[mf], blf);
                    mma16816(acc[mf][nf], al[mf], bhf);
                }
        }
        __syncthreads();
    }

    // ---- epilogue ----
    const float* bg = bias + (size_t)e * N;
    #pragma unroll
    for (int mf = 0; mf < 4; mf++) {
        #pragma unroll
        for (int half = 0; half < 2; half++) {
            int rloc = warpM + mf * 16 + gq + half * 8;
            int gr   = row0 + rloc;
            if (gr >= M) continue;
            #pragma unroll
            for (int nf = 0; nf < 4; nf++) {
                int ncol = col0 + warpN + nf * 8 + 2 * tq;
                float v0 = acc[mf][nf][half * 2 + 0] + bg[ncol];
                float v1 = acc[mf][nf][half * 2 + 1] + bg[ncol + 1];
                if (OMODE == 0) {
                    size_t orow = DENSE ? (size_t)gr : (size_t)g * cap + gr;
                    float2 v; v.x = v0 * alpha; v.y = v1 * alpha;
                    *(float2*)(outF + orow * N + ncol) = v;
                } else if (OMODE == 1) {
                    v0 = fmaxf(v0, 0.f);
                    v1 = fmaxf(v1, 0.f);
                    __nv_bfloat16 h0, l0, h1, l1;
                    bf16_split(v0, h0, l0);
                    bf16_split(v1, h1, l1);
                    __nv_bfloat162 H; H.x = h0; H.y = h1;
                    __nv_bfloat162 L; L.x = l0; L.y = l1;
                    size_t off = ((size_t)g * cap + gr) * N + ncol;
                    *(__nv_bfloat162*)(outH + off) = H;
                    *(__nv_bfloat162*)(outL + off) = L;
                } else if (OMODE == 2) {
                    int tok = rowTok[rloc];
                    float gt = rowG[rloc];
                    float* dst = outF + (size_t)tok * N + ncol;
                    atomicAdd(dst,     gt * v0);
                    atomicAdd(dst + 1, gt * v1);
                } else {   // OMODE 4: kv special (dense)
                    __nv_bfloat16 h0, l0, h1, l1;
                    bf16_split(v0, h0, l0);
                    bf16_split(v1, h1, l1);
                    if (ncol < 128) {
                        __nv_bfloat162 H; H.x = h0; H.y = h1;
                        __nv_bfloat162 L; L.x = l0; L.y = l1;
                        size_t off = (size_t)gr * kHD + ncol;
                        *(__nv_bfloat162*)(outH + off) = H;
                        *(__nv_bfloat162*)(outL + off) = L;
                    } else {
                        int bb = gr >> 10, tl = gr & (kS - 1);
                        int h = ncol - 128;
                        size_t o0 = ((size_t)bb * kHD + h) * kS + tl;
                        size_t o1 = ((size_t)bb * kHD + h + 1) * kS + tl;
                        outH2[o0] = h0; outL2[o0] = l0;
                        outH2[o1] = h1; outL2[o1] = l1;
                    }
                }
            }
        }
    }
}

// ---------------- tensorized attention (QT=32, KT=64, 256 threads) ----------------
namespace {
constexpr int AQT = 32;
constexpr int AKT = 64;
constexpr int QP  = 136;   // q/k smem pitch (bf16)
constexpr int VP  = 72;    // vT / P smem pitch (bf16)
constexpr int SP  = 68;    // S pitch (f32)
constexpr int RP  = 132;   // relq pitch (f32)
// byte offsets
constexpr int OQS  = 0;                       // q f32: 32*128*4 = 16384
constexpr int OQH  = OQS  + 16384;            // 32*QP*2 = 8704
constexpr int OQL  = OQH  + 8704;
constexpr int OKH  = OQL  + 8704;             // 64*QP*2 = 17408
constexpr int OKL  = OKH  + 17408;
constexpr int OVH  = OKL  + 17408;            // 128*VP*2 = 18432
constexpr int OVL  = OVH  + 18432;
constexpr int OPH  = OVL  + 18432;            // 32*VP*2 = 4608
constexpr int OPL  = OPH  + 4608;
constexpr int OSS  = OPL  + 4608;             // 32*SP*4 = 8704
constexpr int OREL = OSS  + 8704;             // 32*RP*4 = 16896
constexpr int OSC  = OREL + 16896;            // 32*4
constexpr int OLL  = OSC  + 128;              // 32*4
constexpr int OQP2 = OLL  + 128;              // qpos 32*4
constexpr int ATTN_SMEM_BYTES = OQP2 + 128;   // 140,800
}

__global__ __launch_bounds__(256)
void attn_kernel(const float* __restrict__ rel_table,
                 __nv_bfloat16* __restrict__ ctxh,
                 __nv_bfloat16* __restrict__ ctxl,
                 const __nv_bfloat16* __restrict__ kbh,
                 const __nv_bfloat16* __restrict__ kbl,
                 const __nv_bfloat16* __restrict__ vTh,
                 const __nv_bfloat16* __restrict__ vTl)
{
    extern __shared__ __align__(16) char sma[];
    float* qs   = (float*)(sma + OQS);
    float* sS   = (float*)(sma + OSS);
    float* relq = (float*)(sma + OREL);
    float* sScale = (float*)(sma + OSC);
    float* sL     = (float*)(sma + OLL);
    int*   qpos   = (int*)(sma + OQP2);

    unsigned smb = smem_u32(sma);
    unsigned uQH = smb + OQH, uQL = smb + OQL;
    unsigned uKH = smb + OKH, uKL = smb + OKL;
    unsigned uVH = smb + OVH, uVL = smb + OVL;
    unsigned uPH = smb + OPH, uPL = smb + OPL;

    int g  = blockIdx.x;
    int b  = g / kEA;
    int qt = blockIdx.y;
    int cnt  = g_cntA[g];
    int base = qt * AQT;
    if (base >= cnt) return;

    int tid  = threadIdx.x;
    int wid  = tid >> 5;
    int lane = tid & 31;
    int gq   = lane >> 2;
    int tq   = lane & 3;

    // ---- load Q f32 (zero-padded) ----
    for (int i = tid; i < AQT * 32; i += 256) {
        int qi = i >> 5, h4 = i & 31;
        float4 v = make_float4(0.f, 0.f, 0.f, 0.f);
        if (base + qi < cnt)
            v = ((const float4*)&g_qg[((size_t)g * kS + base + qi) * kHD])[h4];
        ((float4*)(qs + qi * kHD))[h4] = v;
    }
    if (tid < AQT) {
        int t = (base + tid < cnt) ? g_listA[g * kS + base + tid] : 0;
        qpos[tid] = t & (kS - 1);
    }
    __syncthreads();

    // ---- split Q to bf16 hi/lo smem ----
    for (int i = tid; i < AQT * 64; i += 256) {
        int qi = i >> 6, p = i & 63;
        float v0 = qs[qi * kHD + 2 * p];
        float v1 = qs[qi * kHD + 2 * p + 1];
        __nv_bfloat16 h0, l0, h1, l1;
        bf16_split(v0, h0, l0);
        bf16_split(v1, h1, l1);
        __nv_bfloat162 H; H.x = h0; H.y = h1;
        __nv_bfloat162 L; L.x = l0; L.y = l1;
        *(__nv_bfloat162*)(sma + OQH + (qi * QP + 2 * p) * 2) = H;
        *(__nv_bfloat162*)(sma + OQL + (qi * QP + 2 * p) * 2) = L;
    }
    // ---- relq[qi][r] = q . rel_table[r] ----
    for (int idx = tid; idx < AQT * kR; idx += 256) {
        int qi = idx / kR, r = idx % kR;
        const float4* q4 = (const float4*)(qs + qi * kHD);
        const float4* t4 = (const float4*)&rel_table[(size_t)r * kHD];
        float s = 0.f;
        #pragma unroll
        for (int h = 0; h < kHD / 4; h++) {
            float4 a = q4[h], c = t4[h];
            s += a.x * c.x + a.y * c.y + a.z * c.z + a.w * c.w;
        }
        relq[qi * RP + r] = s;
    }
    __syncthreads();

    // softmax thread mapping
    int sqi = tid >> 3, sli = tid & 7;
    float m = -1e30f, l = 0.f;
    int myq = qpos[sqi];

    // fragment lane offsets (same mapping as GEMM)
    int rowA = (lane & 7) + ((lane >> 3) & 1) * 8;
    int kA   = ((lane >> 4) & 1) * 8;
    int rowB = (lane & 7) + ((lane >> 4) & 1) * 8;
    int kBc  = ((lane >> 3) & 1) * 8;

    int warpM  = (wid & 1) * 16;     // query tile row (m)
    int warpNS = (wid >> 1) * 16;    // score key cols
    int warpNV = (wid >> 1) * 32;    // ctx h cols

    float acc[4][4];
    #pragma unroll
    for (int nf = 0; nf < 4; nf++)
        #pragma unroll
        for (int q = 0; q < 4; q++) acc[nf][q] = 0.f;

    for (int c0 = 0; c0 < kS; c0 += AKT) {
        // ---- load K chunk (64 rows x 128 bf16, hi/lo) ----
        for (int i = tid; i < 1024; i += 256) {
            int r = i >> 4, u = i & 15;
            size_t grow = ((size_t)b * kS + c0 + r) * kHD + u * 8;
            *(uint4*)(sma + OKH + (r * QP + u * 8) * 2) = *(const uint4*)(kbh + grow);
            *(uint4*)(sma + OKL + (r * QP + u * 8) * 2) = *(const uint4*)(kbl + grow);
        }
        // ---- load Vt chunk (128 h-rows x 64 bf16, hi/lo) ----
        for (int i = tid; i < 1024; i += 256) {
            int h = i >> 3, u = i & 7;
            size_t grow = ((size_t)b * kHD + h) * kS + c0 + u * 8;
            *(uint4*)(sma + OVH + (h * VP + u * 8) * 2) = *(const uint4*)(vTh + grow);
            *(uint4*)(sma + OVL + (h * VP + u * 8) * 2) = *(const uint4*)(vTl + grow);
        }
        __syncthreads();

        // ---- scores S[32x64] via HMMA ----
        float sc[2][4];
        #pragma unroll
        for (int nf = 0; nf < 2; nf++)
            #pragma unroll
            for (int q = 0; q < 4; q++) sc[nf][q] = 0.f;
        #pragma unroll
        for (int ks = 0; ks < 8; ks++) {
            int k0 = ks * 16;
            unsigned aqh[4], aql[4], bkh[4], bkl[4];
            unsigned aoff = (unsigned)(((warpM + rowA) * QP + k0 + kA) * 2);
            ldmx4(aqh, uQH + aoff);
            ldmx4(aql, uQL + aoff);
            unsigned boff = (unsigned)(((warpNS + rowB) * QP + k0 + kBc) * 2);
            ldmx4(bkh, uKH + boff);
            ldmx4(bkl, uKL + boff);
            #pragma unroll
            for (int nf = 0; nf < 2; nf++) {
                const unsigned* bhf = &bkh[nf * 2];
                const unsigned* blf = &bkl[nf * 2];
                mma16816(sc[nf], aqh, bhf);
                mma16816(sc[nf], aqh, blf);
                mma16816(sc[nf], aql, bhf);
            }
        }
        #pragma unroll
        for (int nf = 0; nf < 2; nf++) {
            int row = warpM + gq;
            int col = warpNS + nf * 8 + 2 * tq;
            float2 v0; v0.x = sc[nf][0]; v0.y = sc[nf][1];
            float2 v1; v1.x = sc[nf][2]; v1.y = sc[nf][3];
            *(float2*)&sS[row * SP + col]       = v0;
            *(float2*)&sS[(row + 8) * SP + col] = v1;
        }
        __syncthreads();

        // ---- online softmax (8 lanes per query, 8 keys each) ----
        float sv[8], cm = -1e30f;
        #pragma unroll
        for (int j = 0; j < 8; j++) {
            int col = sli + 8 * j;
            float s = sS[sqi * SP + col];
            int rel = c0 + col - myq;
            rel = min(max(rel, -kMAXP), kMAXP) + kMAXP;
            s += relq[sqi * RP + rel];
            sv[j] = s;
            cm = fmaxf(cm, s);
        }
        #pragma unroll
        for (int o = 4; o; o >>= 1) cm = fmaxf(cm, __shfl_xor_sync(~0u, cm, o));
        float mn = fmaxf(m, cm);
        float scale = __expf(m - mn);
        float psum = 0.f;
        #pragma unroll
        for (int j = 0; j < 8; j++) {
            float p = __expf(sv[j] - mn);
            psum += p;
            __nv_bfloat16 ph, pl;
            bf16_split(p, ph, pl);
            int col = sli + 8 * j;
            *(__nv_bfloat16*)(sma + OPH + (sqi * VP + col) * 2) = ph;
            *(__nv_bfloat16*)(sma + OPL + (sqi * VP + col) * 2) = pl;
        }
        #pragma unroll
        for (int o = 4; o; o >>= 1) psum += __shfl_xor_sync(~0u, psum, o);
        l = l * scale + psum;
        m = mn;
        if (sli == 0) { sScale[sqi] = scale; sL[sqi] = l; }
        __syncthreads();

        // ---- PV accumulate (rescale then add) ----
        float s0 = sScale[warpM + gq], s1 = sScale[warpM + gq + 8];
        #pragma unroll
        for (int nf = 0; nf < 4; nf++) {
            acc[nf][0] *= s0; acc[nf][1] *= s0;
            acc[nf][2] *= s1; acc[nf][3] *= s1;
        }
        #pragma unroll
        for (int ks = 0; ks < 4; ks++) {
            int k0 = ks * 16;
            unsigned aph[4], apl[4], bvh[2][4], bvl[2][4];
            unsigned aoff = (unsigned)(((warpM + rowA) * VP + k0 + kA) * 2);
            ldmx4(aph, uPH + aoff);
            ldmx4(apl, uPL + aoff);
            #pragma unroll
            for (int np = 0; np < 2; np++) {
                unsigned boff = (unsigned)(((warpNV + np * 16 + rowB) * VP + k0 + kBc) * 2);
                ldmx4(bvh[np], uVH + boff);
                ldmx4(bvl[np], uVL + boff);
            }
            #pragma unroll
            for (int nf = 0; nf < 4; nf++) {
                const unsigned* bhf = &bvh[nf >> 1][(nf & 1) * 2];
                const unsigned* blf = &bvl[nf >> 1][(nf & 1) * 2];
                mma16816(acc[nf], aph, bhf);
                mma16816(acc[nf], aph, blf);
                mma16816(acc[nf], apl, bhf);
            }
        }
        __syncthreads();
    }

    // ---- output ctx bf16 hi/lo ----
    float li0 = 1.f / sL[warpM + gq];
    float li1 = 1.f / sL[warpM + gq + 8];
    int r0 = base + warpM + gq;
    int r1 = base + warpM + gq + 8;
    #pragma unroll
    for (int nf = 0; nf < 4; nf++) {
        int col = warpNV + nf * 8 + 2 * tq;
        if (r0 < cnt) {
            float v0 = acc[nf][0] * li0, v1 = acc[nf][1] * li0;
            __nv_bfloat16 h0, l0b, h1, l1b;
            bf16_split(v0, h0, l0b);
            bf16_split(v1, h1, l1b);
            __nv_bfloat162 H; H.x = h0; H.y = h1;
            __nv_bfloat162 L; L.x = l0b; L.y = l1b;
            size_t off = ((size_t)g * kS + r0) * kHD + col;
            *(__nv_bfloat162*)(ctxh + off) = H;
            *(__nv_bfloat162*)(ctxl + off) = L;
        }
        if (r1 < cnt) {
            float v0 = acc[nf][2] * li1, v1 = acc[nf][3] * li1;
            __nv_bfloat16 h0, l0b, h1, l1b;
            bf16_split(v0, h0, l0b);
            bf16_split(v1, h1, l1b);
            __nv_bfloat162 H; H.x = h0; H.y = h1;
            __nv_bfloat162 L; L.x = l0b; L.y = l1b;
            size_t off = ((size_t)g * kS + r1) * kHD + col;
            *(__nv_bfloat162*)(ctxh + off) = H;
            *(__nv_bfloat162*)(ctxl + off) = L;
        }
    }
}

// ---------------- launch ----------------
extern "C" void kernel_launch(void* const* d_in, const int* in_sizes, int n_in,
                              void* d_out, int out_size)
{
    const float* src   = (const float*)d_in[0];
    const float* ln1_w = (const float*)d_in[1];
    const float* ln1_b = (const float*)d_in[2];
    const float* ln2_w = (const float*)d_in[3];
    const float* ln2_b = (const float*)d_in[4];
    const float* agw   = (const float*)d_in[5];
    const float* q_w   = (const float*)d_in[6];
    const float* q_b   = (const float*)d_in[7];
    const float* k_w   = (const float*)d_in[8];
    const float* k_b   = (const float*)d_in[9];
    const float* v_w   = (const float*)d_in[10];
    const float* v_b   = (const float*)d_in[11];
    const float* o_w   = (const float*)d_in[12];
    const float* o_b   = (const float*)d_in[13];
    const float* rel   = (const float*)d_in[14];
    const float* fgw   = (const float*)d_in[15];
    const float* w1    = (const float*)d_in[16];
    const float* b1    = (const float*)d_in[17];
    const float* w2    = (const float*)d_in[18];
    const float* b2    = (const float*)d_in[19];
    float* out = (float*)d_out;

    float *xcur, *kvbias, *qg, *gateA, *gateF;
    int *cntA, *listA, *cntF, *listF;
    __nv_bfloat16 *xn1h, *xn1l, *xn2h, *xn2l, *ctxh, *ctxl, *hh, *hl;
    __nv_bfloat16 *w1th, *w1tl, *w2th, *w2tl, *qwth, *qwtl, *owth, *owtl, *kvth, *kvtl;
    __nv_bfloat16 *kbh, *kbl, *vTh, *vTl;
    cudaGetSymbolAddress((void**)&xcur,   g_xcur);
    cudaGetSymbolAddress((void**)&kvbias, g_kvbias);
    cudaGetSymbolAddress((void**)&qg,     g_qg);
    cudaGetSymbolAddress((void**)&gateA,  g_gateA);
    cudaGetSymbolAddress((void**)&gateF,  g_gateF);
    cudaGetSymbolAddress((void**)&cntA,   g_cntA);
    cudaGetSymbolAddress((void**)&listA,  g_listA);
    cudaGetSymbolAddress((void**)&cntF,   g_cntF);
    cudaGetSymbolAddress((void**)&listF,  g_listF);
    cudaGetSymbolAddress((void**)&xn1h,   g_xn1h);
    cudaGetSymbolAddress((void**)&xn1l,   g_xn1l);
    cudaGetSymbolAddress((void**)&xn2h,   g_xn2h);
    cudaGetSymbolAddress((void**)&xn2l,   g_xn2l);
    cudaGetSymbolAddress((void**)&ctxh,   g_ctxh);
    cudaGetSymbolAddress((void**)&ctxl,   g_ctxl);
    cudaGetSymbolAddress((void**)&hh,     g_hh);
    cudaGetSymbolAddress((void**)&hl,     g_hl);
    cudaGetSymbolAddress((void**)&w1th,   g_w1th);
    cudaGetSymbolAddress((void**)&w1tl,   g_w1tl);
    cudaGetSymbolAddress((void**)&w2th,   g_w2th);
    cudaGetSymbolAddress((void**)&w2tl,   g_w2tl);
    cudaGetSymbolAddress((void**)&qwth,   g_qwth);
    cudaGetSymbolAddress((void**)&qwtl,   g_qwtl);
    cudaGetSymbolAddress((void**)&owth,   g_owth);
    cudaGetSymbolAddress((void**)&owtl,   g_owtl);
    cudaGetSymbolAddress((void**)&kvth,   g_kvth);
    cudaGetSymbolAddress((void**)&kvtl,   g_kvtl);
    cudaGetSymbolAddress((void**)&kbh,    g_kbh);
    cudaGetSymbolAddress((void**)&kbl,    g_kbl);
    cudaGetSymbolAddress((void**)&vTh,    g_vTh);
    cudaGetSymbolAddress((void**)&vTl,    g_vTl);

    constexpr int kWmmaSmem = 2 * 4 * 128 * kPAD * 2;   // 81920
    cudaFuncSetAttribute(wmma_gemm_kernel<0, true,  false>,
                         cudaFuncAttributeMaxDynamicSharedMemorySize, kWmmaSmem);
    cudaFuncSetAttribute(wmma_gemm_kernel<4, false, true>,
                         cudaFuncAttributeMaxDynamicSharedMemorySize, kWmmaSmem);
    cudaFuncSetAttribute(wmma_gemm_kernel<1, true,  false>,
                         cudaFuncAttributeMaxDynamicSharedMemorySize, kWmmaSmem);
    cudaFuncSetAttribute(wmma_gemm_kernel<2, false, false>,
                         cudaFuncAttributeMaxDynamicSharedMemorySize, kWmmaSmem);
    cudaFuncSetAttribute(attn_kernel,
                         cudaFuncAttributeMaxDynamicSharedMemorySize, ATTN_SMEM_BYTES);

    zero_cnts_kernel<<<1, 64>>>();
    pack_kvbias_kernel<<<1, 256>>>(k_b, v_b);

    // ---- all weight transposes + splits in ONE launch ----
    transp_all_kernel<<<18688, 256>>>(w1, w2, q_w, o_w, k_w, v_w);

    // ---- LN1 + residual copy (src -> xcur) + attention router ----
    ln_gate_kernel<kEA><<<kBS, 256>>>(src, ln1_w, ln1_b, agw, xn1h, xn1l, xcur,
                                      cntA, listA, gateA, kS, 1);

    // ---- fused k+v projection -> k rows bf16 hi/lo + vT bf16 hi/lo ----
    wmma_gemm_kernel<4, false, true><<<dim3(kBS / 128, 2, 1), 256, kWmmaSmem>>>(
        xn1h, xn1l, kvth, kvtl, kvbias, nullptr, kbh, kbl, vTh, vTl,
        nullptr, nullptr, nullptr, kBS, 256, kD, 0, 1, 1.f);

    // ---- routed q projection (f32 out) ----
    wmma_gemm_kernel<0, true, false><<<dim3(kS / 128, 1, kB * kEA), 256, kWmmaSmem>>>(
        xn1h, xn1l, qwth, qwtl, q_b, qg, nullptr, nullptr, nullptr, nullptr,
        listA, nullptr, cntA, 0, kHD, kD, kS, kEA, kQScale);

    // ---- tensorized attention core ----
    attn_kernel<<<dim3(kB * kEA, kS / AQT), 256, ATTN_SMEM_BYTES>>>(
        rel, ctxh, ctxl, kbh, kbl, vTh, vTl);

    // ---- o-projection: gated atomic scatter into residual ----
    wmma_gemm_kernel<2, false, false><<<dim3(kS / 128, kD / 128, kB * kEA), 256, kWmmaSmem>>>(
        ctxh, ctxl, owth, owtl, o_b, xcur, nullptr, nullptr, nullptr, nullptr,
        listA, gateA, cntA, 0, kD, kHD, kS, kEA, 1.f);

    // ---- LN2 + residual copy (xcur -> out) + FFN router ----
    ln_gate_kernel<kEF><<<kBS, 256>>>(xcur, ln2_w, ln2_b, fgw, xn2h, xn2l, out,
                                      cntF, listF, gateF, kBS, 0);

    // ---- routed FFN up-proj + relu ----
    wmma_gemm_kernel<1, true, false><<<dim3(kBS / 128, kFH / 128, kEF), 256, kWmmaSmem>>>(
        xn2h, xn2l, w1th, w1tl, b1, nullptr, hh, hl, nullptr, nullptr,
        listF, nullptr, cntF, 0, kFH, kD, kBS, kEF, 1.f);

    // ---- FFN down-proj: gated atomic scatter into out ----
    wmma_gemm_kernel<2, false, false><<<dim3(kBS / 128, kD / 128, kEF), 256, kWmmaSmem>>>(
        hh, hl, w2th, w2tl, b2, out, nullptr, nullptr, nullptr, nullptr,
        listF, gateF, cntF, 0, kD, kFH, kBS, kEF, 1.f);
}